// round 10
// baseline (speedup 1.0000x reference)
#include <cuda_runtime.h>
#include <cstdint>

#define DIN   512
#define DOUT  4096
#define CAP   96          // max stored nonzeros per column

#define RB    64          // batch rows per GEMM CTA (2 rows per lane)
#define WARPS 16
#define CPW   64          // columns per warp
#define XPITCH 66         // x-tile pitch (even -> aligned float2, conflict-free)
#define OSP   9           // out-staging pitch

// ---------------- device scratch (static: allocation-free) ----------------
// g_list entries: {byte offset idx*XPITCH*4, fp32 bits of W*mask}, zero-padded
// to a multiple of 4 entries (exact: adding 0.0f is fp32-exact).
__device__ __align__(16) int2  g_list[DOUT * CAP];
__device__            int      g_nnz[DOUT];    // true nnz (clamped to CAP)
__device__            int      g_cnt[DOUT];    // ceil(min(nnz,64)/4) 4-entry groups
__device__ __align__(16) float g_boost[DOUT];

// ---------------- kernel 1: compact sparse lists + boost ----------------
__global__ void k_prep(const float* __restrict__ W, const float* __restrict__ M,
                       const float* __restrict__ duty, const int* __restrict__ kptr) {
    int gt = blockIdx.x * blockDim.x + threadIdx.x;
    if (gt < DOUT) {
        float target = (float)(*kptr) / (float)DOUT;
        g_boost[gt] = expf(0.5f * (target - duty[gt]));
    }
    int j    = blockIdx.x * (blockDim.x >> 5) + (threadIdx.x >> 5);
    int lane = threadIdx.x & 31;
    if (j >= DOUT) return;
    const float* Wr = W + (size_t)j * DIN;
    const float* Mr = M + (size_t)j * DIN;
    int base = 0;
    for (int c = 0; c < DIN / 32; ++c) {
        int i = c * 32 + lane;
        float w = Wr[i] * Mr[i];                 // mask is exactly 0.0 or 1.0
        bool nz = (w != 0.0f);
        unsigned bal = __ballot_sync(0xffffffffu, nz);
        int pos = base + __popc(bal & ((1u << lane) - 1u));
        if (nz && pos < CAP)
            g_list[j * CAP + pos] = make_int2(i * XPITCH * 4, __float_as_int(w));
        base += __popc(bal);
    }
    int n      = (base < 64) ? base : 64;
    int groups = (n + 3) >> 2;                   // 4-entry groups (0..16)
    int npad   = groups * 4;
    if (n + lane < npad)                         // exact zero padding
        g_list[j * CAP + n + lane] = make_int2(0, 0);
    if (lane == 0) {
        g_cnt[j] = groups;
        g_nnz[j] = (base < CAP) ? base : CAP;
    }
}

// ---------------- kernel 2: sparse gather GEMM (fp32 exact) ----------------
// 4 independent FFMA chains, 3-slot list ring prefetched 4 columns ahead,
// counts + bias pre-staged in smem: no LDG on the steady consume path.
__global__ void __launch_bounds__(32 * WARPS, 1)
k_gemm(const float* __restrict__ x, const float* __restrict__ bias,
       float* __restrict__ yout) {
    extern __shared__ float sm[];
    float* xs   = sm;                              // [DIN][XPITCH]
    float* os   = xs + DIN * XPITCH;               // [WARPS][RB][OSP]
    int2*  ring = (int2*)(os + WARPS * RB * OSP);  // [WARPS][3][64]
    int*   scnt = (int*)(ring + WARPS * 3 * 64);   // [1024] group counts
    float* sbia = (float*)(scnt + WARPS * CPW);    // [1024] bias

    int tid  = threadIdx.x;
    int w    = tid >> 5;
    int lane = tid & 31;
    int rowbase = blockIdx.x * RB;
    int colbase = blockIdx.y * (WARPS * CPW);

    const float4* x4 = (const float4*)(x + (size_t)rowbase * DIN);
    for (int t = tid; t < RB * (DIN / 4); t += blockDim.x) {
        int r  = t >> 7;
        int i4 = t & 127;
        float4 v = x4[(size_t)r * (DIN / 4) + i4];
        int ib = i4 * 4;
        xs[(ib + 0) * XPITCH + r] = v.x;
        xs[(ib + 1) * XPITCH + r] = v.y;
        xs[(ib + 2) * XPITCH + r] = v.z;
        xs[(ib + 3) * XPITCH + r] = v.w;
    }
    for (int t = tid; t < WARPS * CPW; t += blockDim.x) {
        scnt[t] = g_cnt[colbase + t];
        sbia[t] = __ldg(&bias[colbase + t]);
    }
    __syncthreads();

    float* osw   = os + w * (RB * OSP);
    int    jwarp = colbase + w * CPW;
    int    jloc0 = w * CPW;
    const char* xbase = (const char*)xs + lane * 8;
    int2*  rng   = ring + w * 3 * 64;

    // prologue: stage cols 0..2 into slots 0..2; reg-hold col 3
    const int2* L;
    int2 rA, rB;
    {
        int2 a0, b0, a1, b1, a2, b2;
        L = &g_list[(size_t)(jwarp + 0) * CAP]; a0 = __ldg(L + lane); b0 = __ldg(L + 32 + lane);
        L = &g_list[(size_t)(jwarp + 1) * CAP]; a1 = __ldg(L + lane); b1 = __ldg(L + 32 + lane);
        L = &g_list[(size_t)(jwarp + 2) * CAP]; a2 = __ldg(L + lane); b2 = __ldg(L + 32 + lane);
        L = &g_list[(size_t)(jwarp + 3) * CAP]; rA = __ldg(L + lane); rB = __ldg(L + 32 + lane);
        rng[0 * 64 + lane] = a0; rng[0 * 64 + 32 + lane] = b0;
        rng[1 * 64 + lane] = a1; rng[1 * 64 + 32 + lane] = b1;
        rng[2 * 64 + lane] = a2; rng[2 * 64 + 32 + lane] = b2;
    }
    __syncwarp();

    int s = 0;   // rotating slot index = ci % 3
    for (int ci = 0; ci < CPW; ++ci) {
        int nb = scnt[jloc0 + ci];                 // 4-entry groups, uniform
        const int4* sb4 = (const int4*)(rng + s * 64);
        float acc00 = 0.f, acc01 = 0.f, acc10 = 0.f, acc11 = 0.f;
        #pragma unroll 4
        for (int t = 0; t < nb; ++t) {
            int4 q0 = sb4[2 * t + 0];
            int4 q1 = sb4[2 * t + 1];
            float2 xa = *(const float2*)(xbase + q0.x);
            float2 xb = *(const float2*)(xbase + q0.z);
            float2 xc = *(const float2*)(xbase + q1.x);
            float2 xd = *(const float2*)(xbase + q1.z);
            acc00 = fmaf(xa.x, __int_as_float(q0.y), acc00);
            acc01 = fmaf(xa.y, __int_as_float(q0.y), acc01);
            acc10 = fmaf(xb.x, __int_as_float(q0.w), acc10);
            acc11 = fmaf(xb.y, __int_as_float(q0.w), acc11);
            acc00 = fmaf(xc.x, __int_as_float(q1.y), acc00);
            acc01 = fmaf(xc.y, __int_as_float(q1.y), acc01);
            acc10 = fmaf(xd.x, __int_as_float(q1.w), acc10);
            acc11 = fmaf(xd.y, __int_as_float(q1.w), acc11);
        }
        if (nb == 16) {                            // ~never: nnz>64 fallback
            int j = jwarp + ci;
            int nn = __ldg(&g_nnz[j]);
            for (int e = 64; e < nn; ++e) {
                int2 pe = __ldg(&g_list[(size_t)j * CAP + e]);
                float2 xv = *(const float2*)(xbase + pe.x);
                acc00 = fmaf(xv.x, __int_as_float(pe.y), acc00);
                acc01 = fmaf(xv.y, __int_as_float(pe.y), acc01);
            }
        }
        float bj = sbia[jloc0 + ci];
        int cc = ci & 7;
        osw[(2 * lane)     * OSP + cc] = (acc00 + acc10) + bj;
        osw[(2 * lane + 1) * OSP + cc] = (acc01 + acc11) + bj;

        // restage this slot with col ci+3 (regs), prefetch col ci+4
        if (ci + 3 < CPW) {
            int2* sb = rng + s * 64;
            sb[lane] = rA; sb[32 + lane] = rB;
            if (ci + 4 < CPW) {
                L = &g_list[(size_t)(jwarp + ci + 4) * CAP];
                rA = __ldg(L + lane); rB = __ldg(L + 32 + lane);
            }
        }

        if (cc == 7) {
            __syncwarp();
            int j0 = jwarp + (ci & ~7);
            #pragma unroll
            for (int q = 0; q < 4; ++q) {
                int chunk = q * 32 + lane;
                int row   = chunk >> 1;
                int c0    = (chunk & 1) * 4;
                float4 v;
                v.x = osw[row * OSP + c0 + 0];
                v.y = osw[row * OSP + c0 + 1];
                v.z = osw[row * OSP + c0 + 2];
                v.w = osw[row * OSP + c0 + 3];
                *(float4*)&yout[(size_t)(rowbase + row) * DOUT + j0 + c0] = v;
            }
        }
        __syncwarp();
        if (++s == 3) s = 0;
    }
}

// ---------------- kernel 3: radix select (512 thr, 8 elems/thread) ----------
__global__ void __launch_bounds__(512)
k_select(float* __restrict__ y, const int* __restrict__ kptr) {
    __shared__ unsigned whist[16 * 256];  // per-warp histograms
    __shared__ unsigned ssum[256];        // suffix sums
    __shared__ unsigned warptot[8];
    __shared__ unsigned s_prefix;
    __shared__ int      s_kk;

    int tid  = threadIdx.x;
    int w    = tid >> 5;
    int lane = tid & 31;
    size_t rowoff = (size_t)blockIdx.x * DOUT;
    const float4* y4 = (const float4*)(y + rowoff);
    const float4* b4 = (const float4*)g_boost;

    float    vreg[8];
    unsigned kreg[8];
    #pragma unroll
    for (int q = 0; q < 2; ++q) {
        int t = tid + 512 * q;
        float4 v  = y4[t];
        float4 bo = b4[t];
        float bv[4] = { v.x * bo.x, v.y * bo.y, v.z * bo.z, v.w * bo.w };
        vreg[q * 4 + 0] = v.x; vreg[q * 4 + 1] = v.y;
        vreg[q * 4 + 2] = v.z; vreg[q * 4 + 3] = v.w;
        #pragma unroll
        for (int e = 0; e < 4; ++e) {
            unsigned u = __float_as_uint(bv[e]);
            kreg[q * 4 + e] = (u & 0x80000000u) ? ~u : (u | 0x80000000u);
        }
    }
    for (int i = tid; i < 16 * 256; i += 512) whist[i] = 0u;
    if (tid == 0) { s_prefix = 0u; s_kk = *kptr; }
    unsigned act = 0xffu;                 // 8-bit active-element mask
    __syncthreads();

    for (int pass = 0; pass < 4; ++pass) {
        int shift = 24 - 8 * pass;
        int kk = s_kk;
        unsigned m = act;
        while (m) {
            int q = __ffs(m) - 1; m &= m - 1;
            atomicAdd(&whist[w * 256 + ((kreg[q] >> shift) & 255)], 1u);
        }
        __syncthreads();
        unsigned v = 0;
        if (tid < 256) {                  // warps 0..7 do the 256-bin scan
            unsigned h = 0;
            #pragma unroll
            for (int ww = 0; ww < 16; ++ww) h += whist[ww * 256 + tid];
            v = h;
            #pragma unroll
            for (int off = 1; off < 32; off <<= 1) {
                unsigned o = __shfl_down_sync(0xffffffffu, v, off);
                if (lane + off < 32) v += o;
            }
            if (lane == 0) warptot[w] = v;
        }
        __syncthreads();
        if (tid < 256) {
            unsigned above = 0;
            #pragma unroll
            for (int ww = 0; ww < 8; ++ww) if (ww > w) above += warptot[ww];
            ssum[tid] = v + above;        // sum over bins >= tid
        }
        for (int i = tid; i < 16 * 256; i += 512) whist[i] = 0u;  // re-zero
        __syncthreads();
        if (tid < 256) {
            unsigned S = ssum[tid];
            unsigned Snext = (tid == 255) ? 0u : ssum[tid + 1];
            if (S >= (unsigned)kk && Snext < (unsigned)kk) {   // one thread
                s_prefix |= ((unsigned)tid) << shift;
                s_kk = kk - (int)Snext;
            }
        }
        __syncthreads();
        unsigned pb = (s_prefix >> shift) & 255u;
        unsigned m2 = act; act = 0u;
        while (m2) {
            int q = __ffs(m2) - 1; m2 &= m2 - 1;
            if (((kreg[q] >> shift) & 255u) == pb) act |= 1u << q;
        }
    }

    unsigned thr = s_prefix;              // exact key of kth largest
    float4* yo4 = (float4*)(y + rowoff);
    #pragma unroll
    for (int q = 0; q < 2; ++q) {
        int t = tid + 512 * q;
        float4 v;
        v.x = (kreg[q * 4 + 0] >= thr) ? vreg[q * 4 + 0] : 0.f;
        v.y = (kreg[q * 4 + 1] >= thr) ? vreg[q * 4 + 1] : 0.f;
        v.z = (kreg[q * 4 + 2] >= thr) ? vreg[q * 4 + 2] : 0.f;
        v.w = (kreg[q * 4 + 3] >= thr) ? vreg[q * 4 + 3] : 0.f;
        yo4[t] = v;
    }
}

// ---------------- launch ----------------
extern "C" void kernel_launch(void* const* d_in, const int* in_sizes, int n_in,
                              void* d_out, int out_size) {
    const float* x    = (const float*)d_in[0];
    const float* W    = (const float*)d_in[1];
    const float* b    = (const float*)d_in[2];
    const float* m    = (const float*)d_in[3];
    const float* duty = (const float*)d_in[4];
    const int*   k    = (const int*)d_in[5];
    float* out = (float*)d_out;

    int B = in_sizes[0] / DIN;   // 16384

    k_prep<<<DOUT / 8, 256>>>(W, m, duty, k);

    const int smem_bytes = (DIN * XPITCH + WARPS * RB * OSP) * (int)sizeof(float)
                         + WARPS * 3 * 64 * (int)sizeof(int2)              // ring 24KB
                         + WARPS * CPW * (int)(sizeof(int) + sizeof(float)); // 8KB
    cudaFuncSetAttribute(k_gemm, cudaFuncAttributeMaxDynamicSharedMemorySize, smem_bytes);
    dim3 grid(B / RB, DOUT / (WARPS * CPW));   // (256, 4)
    k_gemm<<<grid, 32 * WARPS, smem_bytes>>>(x, b, out);

    k_select<<<B, 512>>>(out, k);
}

// round 12
// speedup vs baseline: 1.0024x; 1.0024x over previous
#include <cuda_runtime.h>
#include <cstdint>

#define DIN   512
#define DOUT  4096
#define CAP   96          // max stored nonzeros per column

#define RB    64          // batch rows per GEMM CTA (2 rows per lane)
#define WARPS 16
#define CPW   64          // columns per warp
#define XPITCH 66         // x-tile pitch (even -> aligned float2, conflict-free)
#define OSP   9           // out-staging pitch

// ---------------- device scratch (static: allocation-free) ----------------
// g_list entries: {byte offset idx*XPITCH*4, fp32 bits of W*mask}, zero-padded
// to an even count (exact: adding 0.0f is fp32-exact). The tail [npad,64) is
// NEVER written -> stays zero from static initialization, so over-reading a
// short column during paired processing contributes exact zeros.
__device__ __align__(16) int2  g_list[DOUT * CAP];
__device__            int      g_nnz[DOUT];    // true nnz (clamped to CAP)
__device__            int      g_cnt[DOUT];    // ceil(min(nnz,64)/2) entry PAIRS
__device__ __align__(16) float g_boost[DOUT];

// ---------------- kernel 1: compact sparse lists + boost ----------------
__global__ void k_prep(const float* __restrict__ W, const float* __restrict__ M,
                       const float* __restrict__ duty, const int* __restrict__ kptr) {
    int gt = blockIdx.x * blockDim.x + threadIdx.x;
    if (gt < DOUT) {
        float target = (float)(*kptr) / (float)DOUT;
        g_boost[gt] = expf(0.5f * (target - duty[gt]));
    }
    int j    = blockIdx.x * (blockDim.x >> 5) + (threadIdx.x >> 5);
    int lane = threadIdx.x & 31;
    if (j >= DOUT) return;
    const float* Wr = W + (size_t)j * DIN;
    const float* Mr = M + (size_t)j * DIN;
    int base = 0;
    for (int c = 0; c < DIN / 32; ++c) {
        int i = c * 32 + lane;
        float w = Wr[i] * Mr[i];                 // mask is exactly 0.0 or 1.0
        bool nz = (w != 0.0f);
        unsigned bal = __ballot_sync(0xffffffffu, nz);
        int pos = base + __popc(bal & ((1u << lane) - 1u));
        if (nz && pos < CAP)
            g_list[j * CAP + pos] = make_int2(i * XPITCH * 4, __float_as_int(w));
        base += __popc(bal);
    }
    int n = (base < 64) ? base : 64;
    if (lane == 0) {
        if (n & 1) g_list[j * CAP + n] = make_int2(0, 0);   // exact pad to even
        g_cnt[j] = (n + 1) >> 1;                 // pairs
        g_nnz[j] = (base < CAP) ? base : CAP;
    }
}

// ---------------- kernel 2: sparse gather GEMM (fp32 bit-exact) -------------
// Two COLUMNS processed concurrently; each column's accumulation stays in
// strict index order (bit-identical to the reference's dense in-order sum).
// 4 independent FFMA chains (2 cols x 2 rows). Counts+bias pre-staged; list
// pairs flow via a 2-slot ring (current pair in smem, next pair in regs,
// LDG prefetch 2 pairs ahead).
__global__ void __launch_bounds__(32 * WARPS, 1)
k_gemm(const float* __restrict__ x, const float* __restrict__ bias,
       float* __restrict__ yout) {
    extern __shared__ float sm[];
    float* xs   = sm;                              // [DIN][XPITCH]
    float* os   = xs + DIN * XPITCH;               // [WARPS][RB][OSP]
    int2*  ring = (int2*)(os + WARPS * RB * OSP);  // [WARPS][2][64]
    int*   scnt = (int*)(ring + WARPS * 2 * 64);   // [1024] pair counts
    float* sbia = (float*)(scnt + WARPS * CPW);    // [1024] bias

    int tid  = threadIdx.x;
    int w    = tid >> 5;
    int lane = tid & 31;
    int rowbase = blockIdx.x * RB;
    int colbase = blockIdx.y * (WARPS * CPW);

    const float4* x4 = (const float4*)(x + (size_t)rowbase * DIN);
    for (int t = tid; t < RB * (DIN / 4); t += blockDim.x) {
        int r  = t >> 7;
        int i4 = t & 127;
        float4 v = x4[(size_t)r * (DIN / 4) + i4];
        int ib = i4 * 4;
        xs[(ib + 0) * XPITCH + r] = v.x;
        xs[(ib + 1) * XPITCH + r] = v.y;
        xs[(ib + 2) * XPITCH + r] = v.z;
        xs[(ib + 3) * XPITCH + r] = v.w;
    }
    for (int t = tid; t < WARPS * CPW; t += blockDim.x) {
        scnt[t] = g_cnt[colbase + t];
        sbia[t] = __ldg(&bias[colbase + t]);
    }
    __syncthreads();

    float* osw   = os + w * (RB * OSP);
    int    jwarp = colbase + w * CPW;
    int    jloc0 = w * CPW;
    const char* xbase = (const char*)xs + lane * 8;
    int2*  rng   = ring + w * 2 * 64;              // slot0: even col, slot1: odd

    // prologue: stage pair0 (cols 0,1); reg-hold pair1 (cols 2,3)
    const int2* L;
    int2 rA0, rB0, rA1, rB1;
    {
        int2 a0, b0, a1, b1;
        L = &g_list[(size_t)(jwarp + 0) * CAP]; a0 = __ldg(L + lane); b0 = __ldg(L + 32 + lane);
        L = &g_list[(size_t)(jwarp + 1) * CAP]; a1 = __ldg(L + lane); b1 = __ldg(L + 32 + lane);
        L = &g_list[(size_t)(jwarp + 2) * CAP]; rA0 = __ldg(L + lane); rB0 = __ldg(L + 32 + lane);
        L = &g_list[(size_t)(jwarp + 3) * CAP]; rA1 = __ldg(L + lane); rB1 = __ldg(L + 32 + lane);
        rng[lane] = a0; rng[32 + lane] = b0;
        rng[64 + lane] = a1; rng[96 + lane] = b1;
    }
    __syncwarp();

    for (int pi = 0; pi < CPW / 2; ++pi) {
        int c0 = 2 * pi, c1 = 2 * pi + 1;
        int nbe = scnt[jloc0 + c0];
        int nbo = scnt[jloc0 + c1];
        int nb  = (nbe > nbo) ? nbe : nbo;         // over-read tail is exact 0
        const int4* sbe = (const int4*)(rng);      // even col pairs
        const int4* sbo = (const int4*)(rng + 64); // odd col pairs
        float accE0 = 0.f, accE1 = 0.f, accO0 = 0.f, accO1 = 0.f;
        #pragma unroll 4
        for (int t = 0; t < nb; ++t) {
            int4 qe = sbe[t];
            int4 qo = sbo[t];
            float2 xa = *(const float2*)(xbase + qe.x);
            float2 xb = *(const float2*)(xbase + qe.z);
            float2 xc = *(const float2*)(xbase + qo.x);
            float2 xd = *(const float2*)(xbase + qo.z);
            accE0 = fmaf(xa.x, __int_as_float(qe.y), accE0);   // col even, in order
            accE1 = fmaf(xa.y, __int_as_float(qe.y), accE1);
            accE0 = fmaf(xb.x, __int_as_float(qe.w), accE0);
            accE1 = fmaf(xb.y, __int_as_float(qe.w), accE1);
            accO0 = fmaf(xc.x, __int_as_float(qo.y), accO0);   // col odd, in order
            accO1 = fmaf(xc.y, __int_as_float(qo.y), accO1);
            accO0 = fmaf(xd.x, __int_as_float(qo.w), accO0);
            accO1 = fmaf(xd.y, __int_as_float(qo.w), accO1);
        }
        if (nb == 32) {                            // ~never: nnz>64 fallback
            int je = jwarp + c0, jo = jwarp + c1;
            int ne = __ldg(&g_nnz[je]), no = __ldg(&g_nnz[jo]);
            for (int e = 64; e < ne; ++e) {
                int2 pe = __ldg(&g_list[(size_t)je * CAP + e]);
                float2 xv = *(const float2*)(xbase + pe.x);
                accE0 = fmaf(xv.x, __int_as_float(pe.y), accE0);
                accE1 = fmaf(xv.y, __int_as_float(pe.y), accE1);
            }
            for (int e = 64; e < no; ++e) {
                int2 pe = __ldg(&g_list[(size_t)jo * CAP + e]);
                float2 xv = *(const float2*)(xbase + pe.x);
                accO0 = fmaf(xv.x, __int_as_float(pe.y), accO0);
                accO1 = fmaf(xv.y, __int_as_float(pe.y), accO1);
            }
        }
        float be = sbia[jloc0 + c0];
        float bo = sbia[jloc0 + c1];
        int cc = c0 & 7;
        osw[(2 * lane)     * OSP + cc]     = accE0 + be;
        osw[(2 * lane + 1) * OSP + cc]     = accE1 + be;
        osw[(2 * lane)     * OSP + cc + 1] = accO0 + bo;
        osw[(2 * lane + 1) * OSP + cc + 1] = accO1 + bo;

        // restage slots with next pair (regs), prefetch pair+2
        if (pi + 1 < CPW / 2) {
            rng[lane] = rA0; rng[32 + lane] = rB0;
            rng[64 + lane] = rA1; rng[96 + lane] = rB1;
            if (pi + 2 < CPW / 2) {
                L = &g_list[(size_t)(jwarp + 2 * pi + 4) * CAP];
                rA0 = __ldg(L + lane); rB0 = __ldg(L + 32 + lane);
                L = &g_list[(size_t)(jwarp + 2 * pi + 5) * CAP];
                rA1 = __ldg(L + lane); rB1 = __ldg(L + 32 + lane);
            }
        }

        if ((pi & 3) == 3) {                       // 8 columns ready -> flush
            __syncwarp();
            int j0 = jwarp + (c0 & ~7);
            #pragma unroll
            for (int q = 0; q < 4; ++q) {
                int chunk = q * 32 + lane;
                int row   = chunk >> 1;
                int cb    = (chunk & 1) * 4;
                float4 v;
                v.x = osw[row * OSP + cb + 0];
                v.y = osw[row * OSP + cb + 1];
                v.z = osw[row * OSP + cb + 2];
                v.w = osw[row * OSP + cb + 3];
                *(float4*)&yout[(size_t)(rowbase + row) * DOUT + j0 + cb] = v;
            }
        }
        __syncwarp();
    }
}

// ---------------- kernel 3: radix select (512 thr, 8 elems/thread) ----------
__global__ void __launch_bounds__(512)
k_select(float* __restrict__ y, const int* __restrict__ kptr) {
    __shared__ unsigned whist[16 * 256];  // per-warp histograms
    __shared__ unsigned ssum[256];        // suffix sums
    __shared__ unsigned warptot[8];
    __shared__ unsigned s_prefix;
    __shared__ int      s_kk;

    int tid  = threadIdx.x;
    int w    = tid >> 5;
    int lane = tid & 31;
    size_t rowoff = (size_t)blockIdx.x * DOUT;
    const float4* y4 = (const float4*)(y + rowoff);
    const float4* b4 = (const float4*)g_boost;

    float    vreg[8];
    unsigned kreg[8];
    #pragma unroll
    for (int q = 0; q < 2; ++q) {
        int t = tid + 512 * q;
        float4 v  = y4[t];
        float4 bo = b4[t];
        float bv[4] = { v.x * bo.x, v.y * bo.y, v.z * bo.z, v.w * bo.w };
        vreg[q * 4 + 0] = v.x; vreg[q * 4 + 1] = v.y;
        vreg[q * 4 + 2] = v.z; vreg[q * 4 + 3] = v.w;
        #pragma unroll
        for (int e = 0; e < 4; ++e) {
            unsigned u = __float_as_uint(bv[e]);
            kreg[q * 4 + e] = (u & 0x80000000u) ? ~u : (u | 0x80000000u);
        }
    }
    for (int i = tid; i < 16 * 256; i += 512) whist[i] = 0u;
    if (tid == 0) { s_prefix = 0u; s_kk = *kptr; }
    unsigned act = 0xffu;                 // 8-bit active-element mask
    __syncthreads();

    for (int pass = 0; pass < 4; ++pass) {
        int shift = 24 - 8 * pass;
        int kk = s_kk;
        unsigned m = act;
        while (m) {
            int q = __ffs(m) - 1; m &= m - 1;
            atomicAdd(&whist[w * 256 + ((kreg[q] >> shift) & 255)], 1u);
        }
        __syncthreads();
        unsigned v = 0;
        if (tid < 256) {                  // warps 0..7 do the 256-bin scan
            unsigned h = 0;
            #pragma unroll
            for (int ww = 0; ww < 16; ++ww) h += whist[ww * 256 + tid];
            v = h;
            #pragma unroll
            for (int off = 1; off < 32; off <<= 1) {
                unsigned o = __shfl_down_sync(0xffffffffu, v, off);
                if (lane + off < 32) v += o;
            }
            if (lane == 0) warptot[w] = v;
        }
        __syncthreads();
        if (tid < 256) {
            unsigned above = 0;
            #pragma unroll
            for (int ww = 0; ww < 8; ++ww) if (ww > w) above += warptot[ww];
            ssum[tid] = v + above;        // sum over bins >= tid
        }
        for (int i = tid; i < 16 * 256; i += 512) whist[i] = 0u;  // re-zero
        __syncthreads();
        if (tid < 256) {
            unsigned S = ssum[tid];
            unsigned Snext = (tid == 255) ? 0u : ssum[tid + 1];
            if (S >= (unsigned)kk && Snext < (unsigned)kk) {   // one thread
                s_prefix |= ((unsigned)tid) << shift;
                s_kk = kk - (int)Snext;
            }
        }
        __syncthreads();
        unsigned pb = (s_prefix >> shift) & 255u;
        unsigned m2 = act; act = 0u;
        while (m2) {
            int q = __ffs(m2) - 1; m2 &= m2 - 1;
            if (((kreg[q] >> shift) & 255u) == pb) act |= 1u << q;
        }
    }

    unsigned thr = s_prefix;              // exact key of kth largest
    float4* yo4 = (float4*)(y + rowoff);
    #pragma unroll
    for (int q = 0; q < 2; ++q) {
        int t = tid + 512 * q;
        float4 v;
        v.x = (kreg[q * 4 + 0] >= thr) ? vreg[q * 4 + 0] : 0.f;
        v.y = (kreg[q * 4 + 1] >= thr) ? vreg[q * 4 + 1] : 0.f;
        v.z = (kreg[q * 4 + 2] >= thr) ? vreg[q * 4 + 2] : 0.f;
        v.w = (kreg[q * 4 + 3] >= thr) ? vreg[q * 4 + 3] : 0.f;
        yo4[t] = v;
    }
}

// ---------------- launch ----------------
extern "C" void kernel_launch(void* const* d_in, const int* in_sizes, int n_in,
                              void* d_out, int out_size) {
    const float* x    = (const float*)d_in[0];
    const float* W    = (const float*)d_in[1];
    const float* b    = (const float*)d_in[2];
    const float* m    = (const float*)d_in[3];
    const float* duty = (const float*)d_in[4];
    const int*   k    = (const int*)d_in[5];
    float* out = (float*)d_out;

    int B = in_sizes[0] / DIN;   // 16384

    k_prep<<<DOUT / 8, 256>>>(W, m, duty, k);

    const int smem_bytes = (DIN * XPITCH + WARPS * RB * OSP) * (int)sizeof(float)
                         + WARPS * 2 * 64 * (int)sizeof(int2)              // ring 16KB
                         + WARPS * CPW * (int)(sizeof(int) + sizeof(float)); // 8KB
    cudaFuncSetAttribute(k_gemm, cudaFuncAttributeMaxDynamicSharedMemorySize, smem_bytes);
    dim3 grid(B / RB, DOUT / (WARPS * CPW));   // (256, 4)
    k_gemm<<<grid, 32 * WARPS, smem_bytes>>>(x, b, out);

    k_select<<<B, 512>>>(out, k);
}